// round 13
// baseline (speedup 1.0000x reference)
#include <cuda_runtime.h>
#include <cstdint>

#define CSIZE 4
#define NCTA  128
#define NT    512
#define RWS   16
#define LSEQ  1000

// float-index offsets in dynamic SMEM (identical map to R9)
#define FW1   0          // WT1 [128k][128j]
#define FW2I  16384      // WT2I
#define FW2H  32768      // WT2H
#define FH1D  49152      // h1 dup: [128k][32]  (pairs (h_r,h_r), r=0..15)
#define FH2   53248      // h2:     [128k][16]
#define FGB   55296      // gates:  [16r][132]
#define FBS1  57408      // [4][32]
#define FBS2  57536
#define FWI1  57664
#define FWL   57792      // [128]
#define FXS   57920      // [16]
#define SMEM_SZ (57936 * 4)

typedef unsigned long long ull;

__device__ __forceinline__ ull ffma2(ull a, ull b, ull c) {
    ull d;
    asm("fma.rn.f32x2 %0, %1, %2, %3;" : "=l"(d) : "l"(a), "l"(b), "l"(c));
    return d;
}
__device__ __forceinline__ ull add2(ull a, ull b) {
    ull d;
    asm("add.rn.f32x2 %0, %1, %2;" : "=l"(d) : "l"(a), "l"(b));
    return d;
}
__device__ __forceinline__ ull repf(float v) {
    ull d;
    asm("mov.b64 %0, {%1, %1};" : "=l"(d) : "f"(v));
    return d;
}
__device__ __forceinline__ ull packf2(float lo, float hi) {
    ull d;
    asm("mov.b64 %0, {%1, %2};" : "=l"(d) : "f"(lo), "f"(hi));
    return d;
}
__device__ __forceinline__ float tanhx(float v) {
    float r; asm("tanh.approx.f32 %0, %1;" : "=f"(r) : "f"(v)); return r;
}
__device__ __forceinline__ float sigx(float v) { return fmaf(tanhx(0.5f * v), 0.5f, 0.5f); }

__device__ __forceinline__ uint32_t smem_u32(const void* p) {
    uint32_t a;
    asm("{ .reg .u64 t; cvta.to.shared.u64 t, %1; cvt.u32.u64 %0, t; }" : "=r"(a) : "l"(p));
    return a;
}
__device__ __forceinline__ uint32_t ctarank() {
    uint32_t r; asm("mov.u32 %0, %%cluster_ctarank;" : "=r"(r)); return r;
}
__device__ __forceinline__ void stc64(uint32_t addr, uint32_t rank, ull v) {
    asm volatile("{ .reg .u32 ra; mapa.shared::cluster.u32 ra, %0, %1;"
                 " st.shared::cluster.b64 [ra], %2; }"
                 :: "r"(addr), "r"(rank), "l"(v) : "memory");
}
__device__ __forceinline__ void stc32(uint32_t addr, uint32_t rank, float v) {
    asm volatile("{ .reg .u32 ra; mapa.shared::cluster.u32 ra, %0, %1;"
                 " st.shared::cluster.f32 [ra], %2; }"
                 :: "r"(addr), "r"(rank), "f"(v) : "memory");
}
__device__ __forceinline__ void cl_sync() {
    asm volatile("barrier.cluster.arrive.aligned;" ::: "memory");
    asm volatile("barrier.cluster.wait.aligned;" ::: "memory");
}

// acc[jp*4+rr] += WT[k][j-quad] * h_dup[k][r-quad], k = 0..KN-1
template <int KN>
__device__ __forceinline__ void mv_dup(const float* SF, int wof, int hof,
                                       int jg, int jq, int rq, ull acc[8]) {
    const char* wp = (const char*)(SF + wof + 32 * jg + 4 * jq);
    const char* hp = (const char*)(SF + hof + 8 * rq);
#pragma unroll 8
    for (int k = 0; k < KN; k++) {
        ulonglong2 wv = *(const ulonglong2*)(wp + k * 512);
        ulonglong2 ha = *(const ulonglong2*)(hp + k * 128);
        ulonglong2 hb = *(const ulonglong2*)(hp + k * 128 + 16);
        acc[0] = ffma2(wv.x, ha.x, acc[0]);
        acc[1] = ffma2(wv.x, ha.y, acc[1]);
        acc[2] = ffma2(wv.x, hb.x, acc[2]);
        acc[3] = ffma2(wv.x, hb.y, acc[3]);
        acc[4] = ffma2(wv.y, ha.x, acc[4]);
        acc[5] = ffma2(wv.y, ha.y, acc[5]);
        acc[6] = ffma2(wv.y, hb.x, acc[6]);
        acc[7] = ffma2(wv.y, hb.y, acc[7]);
    }
}

// same but h non-duplicated (h2): replicate via mov
template <int KN>
__device__ __forceinline__ void mv_nodup(const float* SF, int wof, int hof,
                                         int jg, int jq, int rq, ull acc[8]) {
    const char* wp = (const char*)(SF + wof + 32 * jg + 4 * jq);
    const char* hp = (const char*)(SF + hof + 4 * rq);
#pragma unroll 8
    for (int k = 0; k < KN; k++) {
        ulonglong2 wv = *(const ulonglong2*)(wp + k * 512);
        float4 hv = *(const float4*)(hp + k * 64);
        ull h0 = repf(hv.x), h1 = repf(hv.y), h2 = repf(hv.z), h3 = repf(hv.w);
        acc[0] = ffma2(wv.x, h0, acc[0]);
        acc[1] = ffma2(wv.x, h1, acc[1]);
        acc[2] = ffma2(wv.x, h2, acc[2]);
        acc[3] = ffma2(wv.x, h3, acc[3]);
        acc[4] = ffma2(wv.y, h0, acc[4]);
        acc[5] = ffma2(wv.y, h1, acc[5]);
        acc[6] = ffma2(wv.y, h2, acc[6]);
        acc[7] = ffma2(wv.y, h3, acc[7]);
    }
}

__device__ __forceinline__ void gb_put(float* SF, int jg, int jq, int rq,
                                       const ull acc[8], bool addin) {
#pragma unroll
    for (int rr = 0; rr < 4; rr++)
#pragma unroll
        for (int jp = 0; jp < 2; jp++) {
            ull* p = (ull*)(SF + FGB + (4 * rq + rr) * 132 + 32 * jg + 4 * jq + 2 * jp);
            ull v = acc[jp * 4 + rr];
            *p = addin ? add2(*p, v) : v;
        }
}

__global__ void __launch_bounds__(NT, 1) __cluster_dims__(CSIZE, 1, 1)
lstm_t512(const float* __restrict__ x,
          const float* __restrict__ w_ih1, const float* __restrict__ w_hh1,
          const float* __restrict__ b_ih1, const float* __restrict__ b_hh1,
          const float* __restrict__ w_ih2, const float* __restrict__ w_hh2,
          const float* __restrict__ b_ih2, const float* __restrict__ b_hh2,
          const float* __restrict__ w_lin, const float* __restrict__ b_lin,
          float* __restrict__ out)
{
    extern __shared__ float SF[];

    const int tid  = threadIdx.x;
    const uint32_t rank = ctarank();
    const int clus = blockIdx.x >> 2;
    const int row0 = clus * RWS;
    const int UB   = rank * 32;

    const int wid  = tid >> 5;
    const int lane = tid & 31;
    const int jg  = wid & 3;       // gate group
    const int sel = wid >> 2;      // 0..3: mv1 k-quarter; mv2 (mat, k-half)
    const int jq = lane >> 2;      // j quad 0..7
    const int rq = lane & 3;       // r quad 0..3

    // mv1: k-quarter bases
    const int w1of = FW1 + 32 * sel * 128;
    const int h1of = FH1D + 32 * sel * 32;
    // mv2: mat = sel&1 (0: W2I x h1dup, 1: W2H x h2), kh = sel>>1
    const int mat = sel & 1, kh2 = sel >> 1;
    const int w2of = (mat ? FW2H : FW2I) + 64 * kh2 * 128;
    const int h2of = mat ? (FH2 + 64 * kh2 * 16) : (FH1D + 64 * kh2 * 32);

    // ---- one-time: transpose weights to k-major WT[k][128j] ----
    for (int idx = tid; idx < 16384; idx += NT) {
        int j = idx >> 7, k = idx & 127;           // k fast -> coalesced LDG
        int gj = (j >> 5) * 128 + UB + (j & 31);
        SF[FW1  + k * 128 + j] = w_hh1[gj * 128 + k];
        SF[FW2I + k * 128 + j] = w_ih2[gj * 128 + k];
        SF[FW2H + k * 128 + j] = w_hh2[gj * 128 + k];
    }
    for (int i = tid; i < 128; i += NT) {
        int gj = (i >> 5) * 128 + UB + (i & 31);
        SF[FBS1 + i] = b_ih1[gj] + b_hh1[gj];
        SF[FBS2 + i] = b_ih2[gj] + b_hh2[gj];
        SF[FWI1 + i] = w_ih1[gj];
        SF[FWL + i]  = w_lin[i];
    }
    for (int i = tid; i < 4096; i += NT) SF[FH1D + i] = 0.0f;
    for (int i = tid; i < 2048; i += NT) SF[FH2 + i]  = 0.0f;

    const float blin = b_lin[0];
    const uint32_t smb = smem_u32(SF);

    // activation task mapping: one (unit, row) per thread
    const int u = tid >> 4;        // 0..31
    const int r = tid & 15;        // 0..15
    float c1 = 0.f, c2 = 0.f;

    // readout mapping: 8 threads per row (tid < 128)
    const int ro_r = tid >> 3;
    const int ro_u = (tid & 7) * 16;

    __syncthreads();
    cl_sync();

    for (int t = 0; t < LSEQ; t++) {
        if (tid < RWS) SF[FXS + tid] = x[(row0 + tid) * LSEQ + t];

        // ---- mv1: gates1 = h1 @ Whh1^T, 4 k-quarters merged in waves ----
        {
            ull acc[8] = {0, 0, 0, 0, 0, 0, 0, 0};
            mv_dup<32>(SF, w1of, h1of, jg, jq, rq, acc);
            if (sel == 0) gb_put(SF, jg, jq, rq, acc, false);
            __syncthreads();
            if (sel == 1) gb_put(SF, jg, jq, rq, acc, true);
            __syncthreads();
            if (sel == 2) gb_put(SF, jg, jq, rq, acc, true);
            __syncthreads();
            if (sel == 3) gb_put(SF, jg, jq, rq, acc, true);
        }
        cl_sync();   // B1: GB complete; all ranks finished reading h1(t-1)

        // ---- act1: c1/h1 update + cluster broadcast (dup pairs) ----
        {
            float xr = SF[FXS + r];
            float g0 = SF[FGB + r * 132 + u];
            float g1 = SF[FGB + r * 132 + 32 + u];
            float g2 = SF[FGB + r * 132 + 64 + u];
            float g3 = SF[FGB + r * 132 + 96 + u];
            float iv = sigx (fmaf(SF[FWI1 + u],      xr, g0 + SF[FBS1 + u]));
            float fv = sigx (fmaf(SF[FWI1 + 32 + u], xr, g1 + SF[FBS1 + 32 + u]));
            float gv = tanhx(fmaf(SF[FWI1 + 64 + u], xr, g2 + SF[FBS1 + 64 + u]));
            float ov = sigx (fmaf(SF[FWI1 + 96 + u], xr, g3 + SF[FBS1 + 96 + u]));
            c1 = fmaf(fv, c1, iv * gv);
            float h = ov * tanhx(c1);
            ull ph = packf2(h, h);
            uint32_t ad = smb + 4u * (FH1D + (UB + u) * 32 + 2 * r);
#pragma unroll
            for (int rr = 0; rr < CSIZE; rr++) stc64(ad, rr, ph);
        }
        cl_sync();   // B2: h1(t) visible cluster-wide

        // ---- mv2: gates2 = h1 @ Wih2^T + h2 @ Whh2^T, 4 partials in waves ----
        {
            ull acc[8] = {0, 0, 0, 0, 0, 0, 0, 0};
            if (mat == 0) mv_dup<64>(SF, w2of, h2of, jg, jq, rq, acc);
            else          mv_nodup<64>(SF, w2of, h2of, jg, jq, rq, acc);
            if (sel == 0) gb_put(SF, jg, jq, rq, acc, false);
            __syncthreads();
            if (sel == 1) gb_put(SF, jg, jq, rq, acc, true);
            __syncthreads();
            if (sel == 2) gb_put(SF, jg, jq, rq, acc, true);
            __syncthreads();
            if (sel == 3) gb_put(SF, jg, jq, rq, acc, true);
            __syncthreads();
        }

        // ---- readout of step t-1 (reads h2(t-1)) ----
        if (t > 0 && tid < 128) {
            float s = 0.0f;
#pragma unroll
            for (int i = 0; i < 16; i++)
                s = fmaf(SF[FH2 + (ro_u + i) * 16 + ro_r], SF[FWL + ro_u + i], s);
            s += __shfl_xor_sync(0xffffffffu, s, 1);
            s += __shfl_xor_sync(0xffffffffu, s, 2);
            s += __shfl_xor_sync(0xffffffffu, s, 4);
            if ((tid & 7) == 0) out[(row0 + ro_r) * LSEQ + (t - 1)] = s + blin;
        }
        cl_sync();   // B3: all ranks done reading h2(t-1); GB stable for act2

        // ---- act2: c2/h2 update + cluster broadcast ----
        {
            float g0 = SF[FGB + r * 132 + u];
            float g1 = SF[FGB + r * 132 + 32 + u];
            float g2 = SF[FGB + r * 132 + 64 + u];
            float g3 = SF[FGB + r * 132 + 96 + u];
            float iv = sigx (g0 + SF[FBS2 + u]);
            float fv = sigx (g1 + SF[FBS2 + 32 + u]);
            float gv = tanhx(g2 + SF[FBS2 + 64 + u]);
            float ov = sigx (g3 + SF[FBS2 + 96 + u]);
            c2 = fmaf(fv, c2, iv * gv);
            float h = ov * tanhx(c2);
            uint32_t ad = smb + 4u * (FH2 + (UB + u) * 16 + r);
#pragma unroll
            for (int rr = 0; rr < CSIZE; rr++) stc32(ad, rr, h);
        }
        __syncthreads();   // protect GB/XS before next step
    }

    // final readout: h2(L-1)
    cl_sync();
    if (tid < 128) {
        float s = 0.0f;
#pragma unroll
        for (int i = 0; i < 16; i++)
            s = fmaf(SF[FH2 + (ro_u + i) * 16 + ro_r], SF[FWL + ro_u + i], s);
        s += __shfl_xor_sync(0xffffffffu, s, 1);
        s += __shfl_xor_sync(0xffffffffu, s, 2);
        s += __shfl_xor_sync(0xffffffffu, s, 4);
        if ((tid & 7) == 0) out[(row0 + ro_r) * LSEQ + (LSEQ - 1)] = s + blin;
    }
}

extern "C" void kernel_launch(void* const* d_in, const int* in_sizes, int n_in,
                              void* d_out, int out_size) {
    cudaFuncSetAttribute(lstm_t512, cudaFuncAttributeMaxDynamicSharedMemorySize, SMEM_SZ);

    const float* x     = (const float*)d_in[0];
    const float* w_ih1 = (const float*)d_in[1];
    const float* w_hh1 = (const float*)d_in[2];
    const float* b_ih1 = (const float*)d_in[3];
    const float* b_hh1 = (const float*)d_in[4];
    const float* w_ih2 = (const float*)d_in[5];
    const float* w_hh2 = (const float*)d_in[6];
    const float* b_ih2 = (const float*)d_in[7];
    const float* b_hh2 = (const float*)d_in[8];
    const float* w_lin = (const float*)d_in[9];
    const float* b_lin = (const float*)d_in[10];
    float* out = (float*)d_out;

    lstm_t512<<<NCTA, NT, SMEM_SZ>>>(x, w_ih1, w_hh1, b_ih1, b_hh1,
                                     w_ih2, w_hh2, b_ih2, b_hh2,
                                     w_lin, b_lin, out);
}

// round 14
// speedup vs baseline: 1.3437x; 1.3437x over previous
#include <cuda_runtime.h>
#include <cstdint>

#define CSIZE 4
#define NCTA  128
#define NT    512
#define RWS   16
#define LSEQ  1000

// float-index offsets in dynamic SMEM
#define FW1   0          // WT1 [128k][128j]
#define FW2I  16384      // WT2I
#define FW2H  32768      // WT2H
#define FH1   49152      // h1: [128k][16r]
#define FH2   51200      // h2: [128k][16r]
#define FGB   53248      // gates: [16r][276], partial cols at +0 / +140
#define FWL   57664      // [128]
#define FXS   57792      // [16]
#define SMEM_SZ (57808 * 4)

#define GBPAD 276
#define GBCOL 140

typedef unsigned long long ull;

__device__ __forceinline__ ull ffma2(ull a, ull b, ull c) {
    ull d;
    asm("fma.rn.f32x2 %0, %1, %2, %3;" : "=l"(d) : "l"(a), "l"(b), "l"(c));
    return d;
}
__device__ __forceinline__ ull add2(ull a, ull b) {
    ull d;
    asm("add.rn.f32x2 %0, %1, %2;" : "=l"(d) : "l"(a), "l"(b));
    return d;
}
__device__ __forceinline__ ull repf(float v) {
    ull d;
    asm("mov.b64 %0, {%1, %1};" : "=l"(d) : "f"(v));
    return d;
}
__device__ __forceinline__ float tanhx(float v) {
    float r; asm("tanh.approx.f32 %0, %1;" : "=f"(r) : "f"(v)); return r;
}
__device__ __forceinline__ float sigx(float v) { return fmaf(tanhx(0.5f * v), 0.5f, 0.5f); }

__device__ __forceinline__ uint32_t smem_u32(const void* p) {
    uint32_t a;
    asm("{ .reg .u64 t; cvta.to.shared.u64 t, %1; cvt.u32.u64 %0, t; }" : "=r"(a) : "l"(p));
    return a;
}
__device__ __forceinline__ uint32_t ctarank() {
    uint32_t r; asm("mov.u32 %0, %%cluster_ctarank;" : "=r"(r)); return r;
}
__device__ __forceinline__ void stc32(uint32_t addr, uint32_t rank, float v) {
    asm volatile("{ .reg .u32 ra; mapa.shared::cluster.u32 ra, %0, %1;"
                 " st.shared::cluster.f32 [ra], %2; }"
                 :: "r"(addr), "r"(rank), "f"(v) : "memory");
}
__device__ __forceinline__ void cl_sync() {
    asm volatile("barrier.cluster.arrive.aligned;" ::: "memory");
    asm volatile("barrier.cluster.wait.aligned;" ::: "memory");
}

// acc[jp*4+rr] += WT[k][j-quad] * h[k][r-quad]; h replicated via mov
template <int KN>
__device__ __forceinline__ void mv_nodup(const float* SF, int wof, int hof,
                                         int jg, int jq, int rq, ull acc[8]) {
    const char* wp = (const char*)(SF + wof + 32 * jg + 4 * jq);
    const char* hp = (const char*)(SF + hof + 4 * rq);
#pragma unroll 8
    for (int k = 0; k < KN; k++) {
        ulonglong2 wv = *(const ulonglong2*)(wp + k * 512);
        float4 hv = *(const float4*)(hp + k * 64);
        ull h0 = repf(hv.x), h1 = repf(hv.y), h2 = repf(hv.z), h3 = repf(hv.w);
        acc[0] = ffma2(wv.x, h0, acc[0]);
        acc[1] = ffma2(wv.x, h1, acc[1]);
        acc[2] = ffma2(wv.x, h2, acc[2]);
        acc[3] = ffma2(wv.x, h3, acc[3]);
        acc[4] = ffma2(wv.y, h0, acc[4]);
        acc[5] = ffma2(wv.y, h1, acc[5]);
        acc[6] = ffma2(wv.y, h2, acc[6]);
        acc[7] = ffma2(wv.y, h3, acc[7]);
    }
}

// write/RMW partials into GB column 'col' (0 or 1)
__device__ __forceinline__ void gb_put2(float* SF, int col, int jg, int jq, int rq,
                                        const ull acc[8], bool addin) {
#pragma unroll
    for (int rr = 0; rr < 4; rr++) {
        ull* p = (ull*)(SF + FGB + (4 * rq + rr) * GBPAD + col * GBCOL + 32 * jg + 4 * jq);
        if (addin) {
            ulonglong2 old = *(ulonglong2*)p;
            ulonglong2 nv;
            nv.x = add2(old.x, acc[rr]);
            nv.y = add2(old.y, acc[4 + rr]);
            *(ulonglong2*)p = nv;
        } else {
            ulonglong2 nv;
            nv.x = acc[rr];
            nv.y = acc[4 + rr];
            *(ulonglong2*)p = nv;
        }
    }
}

__global__ void __launch_bounds__(NT, 1) __cluster_dims__(CSIZE, 1, 1)
lstm_r14(const float* __restrict__ x,
         const float* __restrict__ w_ih1, const float* __restrict__ w_hh1,
         const float* __restrict__ b_ih1, const float* __restrict__ b_hh1,
         const float* __restrict__ w_ih2, const float* __restrict__ w_hh2,
         const float* __restrict__ b_ih2, const float* __restrict__ b_hh2,
         const float* __restrict__ w_lin, const float* __restrict__ b_lin,
         float* __restrict__ out)
{
    extern __shared__ float SF[];

    const int tid  = threadIdx.x;
    const uint32_t rank = ctarank();
    const int clus = blockIdx.x >> 2;
    const int row0 = clus * RWS;
    const int UB   = rank * 32;

    const int wid  = tid >> 5;
    const int lane = tid & 31;
    const int jg  = wid & 3;       // gate group
    const int sel = wid >> 2;      // 0..3
    const int jq = lane >> 2;      // j quad 0..7
    const int rq = lane & 3;       // r quad 0..3

    // ---- one-time: transpose weights to k-major WT[k][128j] ----
    for (int idx = tid; idx < 16384; idx += NT) {
        int j = idx >> 7, k = idx & 127;           // k fast -> coalesced LDG
        int gj = (j >> 5) * 128 + UB + (j & 31);
        SF[FW1  + k * 128 + j] = w_hh1[gj * 128 + k];
        SF[FW2I + k * 128 + j] = w_ih2[gj * 128 + k];
        SF[FW2H + k * 128 + j] = w_hh2[gj * 128 + k];
    }
    for (int i = tid; i < 128; i += NT) SF[FWL + i] = w_lin[i];
    for (int i = tid; i < 2048; i += NT) { SF[FH1 + i] = 0.0f; SF[FH2 + i] = 0.0f; }

    // activation task mapping: one (unit, row) per thread; consts in registers
    const int u = tid >> 4;        // 0..31
    const int r = tid & 15;        // 0..15
    float b1c[4], b2c[4], wic[4];
#pragma unroll
    for (int g = 0; g < 4; g++) {
        int gj = g * 128 + UB + u;
        b1c[g] = b_ih1[gj] + b_hh1[gj];
        b2c[g] = b_ih2[gj] + b_hh2[gj];
        wic[g] = w_ih1[gj];
    }
    float c1 = 0.f, c2 = 0.f;
    const float blin = b_lin[0];
    const uint32_t smb = smem_u32(SF);

    // readout mapping: 8 threads per row (tid < 128)
    const int ro_r = tid >> 3;
    const int ro_u = (tid & 7) * 16;

    // mv2 role
    const int mat = sel & 1, kh2 = sel >> 1;
    const int w2of = (mat ? FW2H : FW2I) + 64 * kh2 * 128;
    const int h2of = (mat ? FH2 : FH1) + 64 * kh2 * 16;

    __syncthreads();
    cl_sync();

    for (int t = 0; t < LSEQ; t++) {
        float xv = 0.0f;
        if (tid < RWS) xv = x[(row0 + tid) * LSEQ + t];
        __syncthreads();                 // S0: act2(t-1) finished reading GB

        // ---- mv1: gates1 = h1 @ Whh1^T (4 k-quarters, 2 columns x 2 waves) ----
        {
            ull acc[8] = {0, 0, 0, 0, 0, 0, 0, 0};
            mv_nodup<32>(SF, FW1 + 32 * sel * 128, FH1 + 32 * sel * 16, jg, jq, rq, acc);
            if (sel < 2) gb_put2(SF, sel, jg, jq, rq, acc, false);
            __syncthreads();             // S1
            if (sel >= 2) gb_put2(SF, sel - 2, jg, jq, rq, acc, true);
        }
        if (tid < RWS) SF[FXS + tid] = xv;
        cl_sync();                       // A: GB done; all ranks past mv1 reads of h1

        // ---- act1 -> h1(t) broadcast ----
        {
            float xr = SF[FXS + r];
            const float* gb = SF + FGB + r * GBPAD;
            float g0 = gb[u]      + gb[GBCOL + u];
            float g1 = gb[32 + u] + gb[GBCOL + 32 + u];
            float g2 = gb[64 + u] + gb[GBCOL + 64 + u];
            float g3 = gb[96 + u] + gb[GBCOL + 96 + u];
            float iv = sigx (fmaf(wic[0], xr, g0 + b1c[0]));
            float fv = sigx (fmaf(wic[1], xr, g1 + b1c[1]));
            float gv = tanhx(fmaf(wic[2], xr, g2 + b1c[2]));
            float ov = sigx (fmaf(wic[3], xr, g3 + b1c[3]));
            c1 = fmaf(fv, c1, iv * gv);
            float h = ov * tanhx(c1);
            uint32_t ad = smb + 4u * (FH1 + (UB + u) * 16 + r);
#pragma unroll
            for (int rr = 0; rr < CSIZE; rr++) stc32(ad, rr, h);
        }
        cl_sync();                       // B: h1(t) visible cluster-wide

        // ---- mv2: gates2 = h1 @ Wih2^T + h2 @ Whh2^T (2 mats x 2 k-halves) ----
        {
            ull acc[8] = {0, 0, 0, 0, 0, 0, 0, 0};
            mv_nodup<64>(SF, w2of, h2of, jg, jq, rq, acc);
            if (kh2 == 0) gb_put2(SF, mat, jg, jq, rq, acc, false);
            __syncthreads();             // S2
            if (kh2 == 1) gb_put2(SF, mat, jg, jq, rq, acc, true);
        }

        // ---- readout of step t-1 (reads h2(t-1)) ----
        if (t > 0 && tid < 128) {
            float s = 0.0f;
#pragma unroll
            for (int i = 0; i < 16; i++)
                s = fmaf(SF[FH2 + (ro_u + i) * 16 + ro_r], SF[FWL + ro_u + i], s);
            s += __shfl_xor_sync(0xffffffffu, s, 1);
            s += __shfl_xor_sync(0xffffffffu, s, 2);
            s += __shfl_xor_sync(0xffffffffu, s, 4);
            if ((tid & 7) == 0) out[(row0 + ro_r) * LSEQ + (t - 1)] = s + blin;
        }
        cl_sync();                       // C: GB done; all ranks done reading h2(t-1)

        // ---- act2 -> h2(t) broadcast ----
        {
            const float* gb = SF + FGB + r * GBPAD;
            float g0 = gb[u]      + gb[GBCOL + u];
            float g1 = gb[32 + u] + gb[GBCOL + 32 + u];
            float g2 = gb[64 + u] + gb[GBCOL + 64 + u];
            float g3 = gb[96 + u] + gb[GBCOL + 96 + u];
            float iv = sigx (g0 + b2c[0]);
            float fv = sigx (g1 + b2c[1]);
            float gv = tanhx(g2 + b2c[2]);
            float ov = sigx (g3 + b2c[3]);
            c2 = fmaf(fv, c2, iv * gv);
            float h = ov * tanhx(c2);
            uint32_t ad = smb + 4u * (FH2 + (UB + u) * 16 + r);
#pragma unroll
            for (int rr = 0; rr < CSIZE; rr++) stc32(ad, rr, h);
        }
    }

    // final readout: h2(L-1)
    cl_sync();
    if (tid < 128) {
        float s = 0.0f;
#pragma unroll
        for (int i = 0; i < 16; i++)
            s = fmaf(SF[FH2 + (ro_u + i) * 16 + ro_r], SF[FWL + ro_u + i], s);
        s += __shfl_xor_sync(0xffffffffu, s, 1);
        s += __shfl_xor_sync(0xffffffffu, s, 2);
        s += __shfl_xor_sync(0xffffffffu, s, 4);
        if ((tid & 7) == 0) out[(row0 + ro_r) * LSEQ + (LSEQ - 1)] = s + blin;
    }
}

extern "C" void kernel_launch(void* const* d_in, const int* in_sizes, int n_in,
                              void* d_out, int out_size) {
    cudaFuncSetAttribute(lstm_r14, cudaFuncAttributeMaxDynamicSharedMemorySize, SMEM_SZ);

    const float* x     = (const float*)d_in[0];
    const float* w_ih1 = (const float*)d_in[1];
    const float* w_hh1 = (const float*)d_in[2];
    const float* b_ih1 = (const float*)d_in[3];
    const float* b_hh1 = (const float*)d_in[4];
    const float* w_ih2 = (const float*)d_in[5];
    const float* w_hh2 = (const float*)d_in[6];
    const float* b_ih2 = (const float*)d_in[7];
    const float* b_hh2 = (const float*)d_in[8];
    const float* w_lin = (const float*)d_in[9];
    const float* b_lin = (const float*)d_in[10];
    float* out = (float*)d_out;

    lstm_r14<<<NCTA, NT, SMEM_SZ>>>(x, w_ih1, w_hh1, b_ih1, b_hh1,
                                    w_ih2, w_hh2, b_ih2, b_hh2,
                                    w_lin, b_lin, out);
}